// round 1
// baseline (speedup 1.0000x reference)
#include <cuda_runtime.h>

// TransD scoring kernel.
// out[b] = rp * (dot(hp,h) - dot(tp,t)) + (h - t) + r
// ENT_DIM = REL_DIM = 128, BATCH = 16384.
//
// One warp per batch element. Each lane owns 4 consecutive floats (float4).
// Entity gathers (h, hp, t, tp) are random rows of a 512MB table -> DRAM.
// Relation tables are 512KB each -> L2 resident.

#define ENT_DIM 128
#define BATCH 16384

__device__ __forceinline__ float warp_sum(float v) {
    v += __shfl_xor_sync(0xFFFFFFFFu, v, 16);
    v += __shfl_xor_sync(0xFFFFFFFFu, v, 8);
    v += __shfl_xor_sync(0xFFFFFFFFu, v, 4);
    v += __shfl_xor_sync(0xFFFFFFFFu, v, 2);
    v += __shfl_xor_sync(0xFFFFFFFFu, v, 1);
    return v;
}

__global__ __launch_bounds__(256, 8)
void transd_kernel(const int* __restrict__ head,
                   const int* __restrict__ relation,
                   const int* __restrict__ tail,
                   const float4* __restrict__ ent_emb,
                   const float4* __restrict__ ent_map_emb,
                   const float4* __restrict__ rel_emb,
                   const float4* __restrict__ rel_map_emb,
                   float4* __restrict__ out)
{
    const int warp_id = (blockIdx.x * blockDim.x + threadIdx.x) >> 5;
    const int lane    = threadIdx.x & 31;
    if (warp_id >= BATCH) return;

    const int hidx = head[warp_id];
    const int tidx = tail[warp_id];
    const int ridx = relation[warp_id];

    // Row of 128 floats = 32 float4; lane owns float4 #lane.
    const long hoff = (long)hidx * 32 + lane;
    const long toff = (long)tidx * 32 + lane;
    const long roff = (long)ridx * 32 + lane;

    // Issue all independent gathers up front for MLP.
    const float4 h  = __ldg(&ent_emb[hoff]);
    const float4 t  = __ldg(&ent_emb[toff]);
    const float4 hp = __ldg(&ent_map_emb[hoff]);
    const float4 tp = __ldg(&ent_map_emb[toff]);
    const float4 r  = __ldg(&rel_emb[roff]);
    const float4 rp = __ldg(&rel_map_emb[roff]);

    float dh = h.x * hp.x + h.y * hp.y + h.z * hp.z + h.w * hp.w;
    float dt = t.x * tp.x + t.y * tp.y + t.z * tp.z + t.w * tp.w;

    // Single reduction of (dh - dt).
    const float d = warp_sum(dh - dt);

    float4 o;
    o.x = fmaf(rp.x, d, h.x - t.x + r.x);
    o.y = fmaf(rp.y, d, h.y - t.y + r.y);
    o.z = fmaf(rp.z, d, h.z - t.z + r.z);
    o.w = fmaf(rp.w, d, h.w - t.w + r.w);

    out[(long)warp_id * 32 + lane] = o;
}

extern "C" void kernel_launch(void* const* d_in, const int* in_sizes, int n_in,
                              void* d_out, int out_size)
{
    const int*    head    = (const int*)d_in[0];
    const int*    rel     = (const int*)d_in[1];
    const int*    tail    = (const int*)d_in[2];
    const float4* ent     = (const float4*)d_in[3];
    const float4* ent_map = (const float4*)d_in[4];
    const float4* rel_emb = (const float4*)d_in[5];
    const float4* rel_map = (const float4*)d_in[6];
    float4*       out     = (float4*)d_out;

    // BATCH warps, 8 warps per block.
    const int threads = 256;
    const int blocks  = (BATCH * 32) / threads;  // 2048
    transd_kernel<<<blocks, threads>>>(head, rel, tail, ent, ent_map,
                                       rel_emb, rel_map, out);
}

// round 2
// speedup vs baseline: 1.0036x; 1.0036x over previous
#include <cuda_runtime.h>

// TransD scoring kernel, round 2.
// out[b] = rp * (dot(hp,h) - dot(tp,t)) + (h - t) + r
// ENT_DIM = REL_DIM = 128, BATCH = 16384.
//
// One warp handles TWO batch elements -> 8 independent 512B entity gathers
// in flight per warp (vs 4 in R1) to cover DRAM latency. Lane owns one
// float4 (16B) of each 128-float row; every row access is one fully
// coalesced 512B warp transaction.

#define BATCH 16384
#define ELEMS_PER_WARP 2

__device__ __forceinline__ float warp_sum(float v) {
    v += __shfl_xor_sync(0xFFFFFFFFu, v, 16);
    v += __shfl_xor_sync(0xFFFFFFFFu, v, 8);
    v += __shfl_xor_sync(0xFFFFFFFFu, v, 4);
    v += __shfl_xor_sync(0xFFFFFFFFu, v, 2);
    v += __shfl_xor_sync(0xFFFFFFFFu, v, 1);
    return v;
}

__global__ __launch_bounds__(256, 4)
void transd_kernel(const int* __restrict__ head,
                   const int* __restrict__ relation,
                   const int* __restrict__ tail,
                   const float4* __restrict__ ent_emb,
                   const float4* __restrict__ ent_map_emb,
                   const float4* __restrict__ rel_emb,
                   const float4* __restrict__ rel_map_emb,
                   float4* __restrict__ out)
{
    const int warp_id = (blockIdx.x * blockDim.x + threadIdx.x) >> 5;
    const int lane    = threadIdx.x & 31;

    const int b0 = warp_id * ELEMS_PER_WARP;
    const int b1 = b0 + 1;
    if (b0 >= BATCH) return;

    const int h0 = head[b0],     h1 = head[b1];
    const int t0 = tail[b0],     t1 = tail[b1];
    const int r0 = relation[b0], r1 = relation[b1];

    const long ho0 = (long)h0 * 32 + lane;
    const long to0 = (long)t0 * 32 + lane;
    const long ho1 = (long)h1 * 32 + lane;
    const long to1 = (long)t1 * 32 + lane;
    const long ro0 = (long)r0 * 32 + lane;
    const long ro1 = (long)r1 * 32 + lane;

    // 8 independent DRAM gathers issued before any use (MLP=8),
    // plus 4 L2-resident relation loads.
    const float4 vh0  = __ldg(&ent_emb[ho0]);
    const float4 vt0  = __ldg(&ent_emb[to0]);
    const float4 vh1  = __ldg(&ent_emb[ho1]);
    const float4 vt1  = __ldg(&ent_emb[to1]);
    const float4 vhp0 = __ldg(&ent_map_emb[ho0]);
    const float4 vtp0 = __ldg(&ent_map_emb[to0]);
    const float4 vhp1 = __ldg(&ent_map_emb[ho1]);
    const float4 vtp1 = __ldg(&ent_map_emb[to1]);
    const float4 vr0  = __ldg(&rel_emb[ro0]);
    const float4 vr1  = __ldg(&rel_emb[ro1]);
    const float4 vrp0 = __ldg(&rel_map_emb[ro0]);
    const float4 vrp1 = __ldg(&rel_map_emb[ro1]);

    float dh0 = vh0.x * vhp0.x + vh0.y * vhp0.y + vh0.z * vhp0.z + vh0.w * vhp0.w;
    float dt0 = vt0.x * vtp0.x + vt0.y * vtp0.y + vt0.z * vtp0.z + vt0.w * vtp0.w;
    float dh1 = vh1.x * vhp1.x + vh1.y * vhp1.y + vh1.z * vhp1.z + vh1.w * vhp1.w;
    float dt1 = vt1.x * vtp1.x + vt1.y * vtp1.y + vt1.z * vtp1.z + vt1.w * vtp1.w;

    const float d0 = warp_sum(dh0 - dt0);
    const float d1 = warp_sum(dh1 - dt1);

    float4 o0, o1;
    o0.x = fmaf(vrp0.x, d0, vh0.x - vt0.x + vr0.x);
    o0.y = fmaf(vrp0.y, d0, vh0.y - vt0.y + vr0.y);
    o0.z = fmaf(vrp0.z, d0, vh0.z - vt0.z + vr0.z);
    o0.w = fmaf(vrp0.w, d0, vh0.w - vt0.w + vr0.w);
    o1.x = fmaf(vrp1.x, d1, vh1.x - vt1.x + vr1.x);
    o1.y = fmaf(vrp1.y, d1, vh1.y - vt1.y + vr1.y);
    o1.z = fmaf(vrp1.z, d1, vh1.z - vt1.z + vr1.z);
    o1.w = fmaf(vrp1.w, d1, vh1.w - vt1.w + vr1.w);

    out[(long)b0 * 32 + lane] = o0;
    out[(long)b1 * 32 + lane] = o1;
}

extern "C" void kernel_launch(void* const* d_in, const int* in_sizes, int n_in,
                              void* d_out, int out_size)
{
    const int*    head    = (const int*)d_in[0];
    const int*    rel     = (const int*)d_in[1];
    const int*    tail    = (const int*)d_in[2];
    const float4* ent     = (const float4*)d_in[3];
    const float4* ent_map = (const float4*)d_in[4];
    const float4* rel_emb = (const float4*)d_in[5];
    const float4* rel_map = (const float4*)d_in[6];
    float4*       out     = (float4*)d_out;

    const int threads = 256;                       // 8 warps -> 16 batch elems/block
    const int blocks  = BATCH / (8 * ELEMS_PER_WARP);  // 1024
    transd_kernel<<<blocks, threads>>>(head, rel, tail, ent, ent_map,
                                       rel_emb, rel_map, out);
}